// round 15
// baseline (speedup 1.0000x reference)
#include <cuda_runtime.h>
#include <cstdint>

#define BS_   2
#define SEQ   2048
#define HID   1024
#define HEADS 16
#define HD    64
#define NTOK  (BS_*SEQ)   // 4096

// Scratch (allocation-free rule: __device__ globals)
__device__ float g_Q[NTOK*HID];
__device__ float g_K[NTOK*HID];
__device__ float g_V[NTOK*HID];
__device__ float g_A[NTOK*HID];

// ===========================================================================
// helpers
// ===========================================================================
__device__ __forceinline__ uint32_t smem_u32(const void* p) {
    uint32_t a;
    asm("{ .reg .u64 t; cvta.to.shared.u64 t, %1; cvt.u32.u64 %0, t; }"
        : "=r"(a) : "l"(p));
    return a;
}
__device__ __forceinline__ void cp_async16(uint32_t dst, const void* src) {
    asm volatile("cp.async.cg.shared.global [%0], [%1], 16;"
                 :: "r"(dst), "l"(src) : "memory");
}
#define CP_COMMIT() asm volatile("cp.async.commit_group;" ::: "memory")
#define CP_WAIT(n)  asm volatile("cp.async.wait_group %0;" :: "n"(n) : "memory")

// round-to-nearest fp32 -> tf32
__device__ __forceinline__ uint32_t f2tf32(float f) {
    uint32_t r;
    asm("cvt.rna.tf32.f32 %0, %1;" : "=r"(r) : "f"(f));
    return r;
}

// m16n8k8 tf32 MMA (A row-major, B col-major), fp32 accum
// A frag: a0=(gid,tg) a1=(gid+8,tg) a2=(gid,tg+4) a3=(gid+8,tg+4)
// B frag: b0=(k=tg,n=gid) b1=(k=tg+4,n=gid)
// C frag: c0=(gid,2tg) c1=(gid,2tg+1) c2=(gid+8,2tg) c3=(gid+8,2tg+1)
__device__ __forceinline__ void mma_tf32(float* c, const uint32_t* a,
                                         const uint32_t* b) {
    asm volatile(
        "mma.sync.aligned.m16n8k8.row.col.f32.tf32.tf32.f32 "
        "{%0,%1,%2,%3}, {%4,%5,%6,%7}, {%8,%9}, {%0,%1,%2,%3};"
        : "+f"(c[0]), "+f"(c[1]), "+f"(c[2]), "+f"(c[3])
        : "r"(a[0]), "r"(a[1]), "r"(a[2]), "r"(a[3]), "r"(b[0]), "r"(b[1]));
}

// ===========================================================================
// TF32 mma.sync GEMM: C[M,N] = A[M,K] * B[N,K]^T + bias   (UNCHANGED — control)
// ===========================================================================
#define BM  128
#define BN  128
#define BK  32
#define LDP (BK + 4)
#define TILE_F (BM * LDP)
#define GM_SMEM (4 * TILE_F * (int)sizeof(float))

__global__ void __launch_bounds__(256) gemm_tf32_kernel(
    const float* __restrict__ A, const float* __restrict__ B,
    const float* __restrict__ bias, float* __restrict__ C)
{
    constexpr int N = HID, K = HID;
    constexpr int NT = K / BK;
    extern __shared__ float sm[];
    float* As = sm;
    float* Bs = sm + 2 * TILE_F;

    const int tid  = threadIdx.x;
    const int wid  = tid >> 5, lane = tid & 31;
    const int wm   = wid >> 2, wn = wid & 3;
    const int gid  = lane >> 2, tg = lane & 3;
    const int brow = blockIdx.y * BM;
    const int bcol = blockIdx.x * BN;

    float acc[4][4][4];
    #pragma unroll
    for (int i = 0; i < 4; i++)
        #pragma unroll
        for (int j = 0; j < 4; j++)
            #pragma unroll
            for (int e = 0; e < 4; e++) acc[i][j][e] = 0.f;

    const uint32_t sA0 = smem_u32(As);
    const uint32_t sB0 = smem_u32(Bs);

    auto load_tile = [&](int buf, int k0) {
        const uint32_t dA = sA0 + buf * TILE_F * 4;
        const uint32_t dB = sB0 + buf * TILE_F * 4;
        #pragma unroll
        for (int i = 0; i < 4; i++) {
            int idx = tid + i * 256;
            int row = idx >> 3, c4 = idx & 7;
            cp_async16(dA + (row * LDP + c4 * 4) * 4,
                       A + (size_t)(brow + row) * K + k0 + c4 * 4);
            cp_async16(dB + (row * LDP + c4 * 4) * 4,
                       B + (size_t)(bcol + row) * K + k0 + c4 * 4);
        }
        CP_COMMIT();
    };

    load_tile(0, 0);

    for (int t = 0; t < NT; t++) {
        const int cur = t & 1;
        if (t + 1 < NT) { load_tile(1 - cur, (t + 1) * BK); CP_WAIT(1); }
        else            { CP_WAIT(0); }
        __syncthreads();

        const float* wA = As + cur * TILE_F + (wm * 64) * LDP;
        const float* wB = Bs + cur * TILE_F + (wn * 32) * LDP;

        #pragma unroll
        for (int ks = 0; ks < 4; ks++) {
            const int kb = ks * 8;
            uint32_t a[4][4], b[4][2];
            #pragma unroll
            for (int mt = 0; mt < 4; mt++) {
                const float* p = wA + (mt * 16 + gid) * LDP + kb + tg;
                a[mt][0] = f2tf32(p[0]);
                a[mt][1] = f2tf32(p[8 * LDP]);
                a[mt][2] = f2tf32(p[4]);
                a[mt][3] = f2tf32(p[8 * LDP + 4]);
            }
            #pragma unroll
            for (int nt = 0; nt < 4; nt++) {
                const float* p = wB + (nt * 8 + gid) * LDP + kb + tg;
                b[nt][0] = f2tf32(p[0]);
                b[nt][1] = f2tf32(p[4]);
            }
            #pragma unroll
            for (int mt = 0; mt < 4; mt++)
                #pragma unroll
                for (int nt = 0; nt < 4; nt++)
                    mma_tf32(acc[mt][nt], a[mt], b[nt]);
        }
        __syncthreads();
    }

    const int rbase = brow + wm * 64;
    const int cbase = bcol + wn * 32;
    #pragma unroll
    for (int mt = 0; mt < 4; mt++) {
        #pragma unroll
        for (int nt = 0; nt < 4; nt++) {
            const int r0 = rbase + mt * 16 + gid;
            const int c0 = cbase + nt * 8 + tg * 2;
            float2 bv = *(const float2*)(bias + c0);
            float2 v0 = { acc[mt][nt][0] + bv.x, acc[mt][nt][1] + bv.y };
            float2 v1 = { acc[mt][nt][2] + bv.x, acc[mt][nt][3] + bv.y };
            *(float2*)(C + (size_t)r0 * N + c0)       = v0;
            *(float2*)(C + (size_t)(r0 + 8) * N + c0) = v1;
        }
    }
}

// ===========================================================================
// Flash attention, tf32 mma.sync.
// R15: 128 q-rows per CTA, 8 warps (R13 inner loop restored: fp32 SMEM,
// cvt at fragment load). Each staged K/V tile feeds 2x the MMA work;
// 16 warps/SM (2 CTAs x 8) vs 10.5 before.
// Block-causal: kv tiles 0..2qt all warps; tile 2qt+1 only warps 4-7.
// ===========================================================================
#define ALD 68
#define QROWS 128
#define AT_SMEM ((QROWS + 64 + 64 + QROWS) * ALD * (int)sizeof(float)) // 104448B

__global__ void __launch_bounds__(256) attn_kernel(
    const float* __restrict__ Q, const float* __restrict__ K,
    const float* __restrict__ V, float* __restrict__ O)
{
    extern __shared__ float smf[];
    float* Qs = smf;                    // [128][ALD]
    float* Ks = Qs + QROWS * ALD;       // [64][ALD]
    float* Vs = Ks + 64 * ALD;          // [64][ALD]
    float* Ps = Vs + 64 * ALD;          // [128][ALD]

    const int qt = blockIdx.x, h = blockIdx.y, b = blockIdx.z;
    const int tid = threadIdx.x, wid = tid >> 5, lane = tid & 31;
    const int gid = lane >> 2, tg = lane & 3;
    const int mbase = wid * 16;

    // Load Q tile (128 rows) pre-scaled by 1/sqrt(64)
    const float* qbase = Q + ((size_t)(b * SEQ + qt * QROWS)) * HID + h * HD;
    for (int i = tid; i < QROWS * 16; i += 256) {
        int r = i >> 4, c4 = i & 15;
        float4 v = *(const float4*)(qbase + (size_t)r * HID + c4 * 4);
        v.x *= 0.125f; v.y *= 0.125f; v.z *= 0.125f; v.w *= 0.125f;
        *(float4*)(Qs + r * ALD + c4 * 4) = v;
    }

    float m0 = -1e30f, m1 = -1e30f, l0 = 0.f, l1 = 0.f;
    float o[8][4];
    #pragma unroll
    for (int i = 0; i < 8; i++)
        #pragma unroll
        for (int e = 0; e < 4; e++) o[i][e] = 0.f;

    const int nkt = 2 * qt + 2;   // kv tiles: 0..2qt+1 (last one half-masked)
    for (int kt = 0; kt < nkt; kt++) {
        __syncthreads();
        const float* kbase = K + ((size_t)(b * SEQ + kt * 64)) * HID + h * HD;
        const float* vbase = V + ((size_t)(b * SEQ + kt * 64)) * HID + h * HD;
        for (int i = tid; i < 64 * 16; i += 256) {
            int r = i >> 4, c4 = i & 15;
            *(float4*)(Ks + r * ALD + c4 * 4) =
                *(const float4*)(kbase + (size_t)r * HID + c4 * 4);
            *(float4*)(Vs + r * ALD + c4 * 4) =
                *(const float4*)(vbase + (size_t)r * HID + c4 * 4);
        }
        __syncthreads();

        // last kv tile (2qt+1) is causal-visible only to q-rows 64..127
        const bool active = (kt <= 2 * qt) || (wid >= 4);
        if (active) {
            // ---- S = Qs * Ks^T  (per-warp m16 x n64, k=64) ----
            float s[8][4];
            #pragma unroll
            for (int i = 0; i < 8; i++)
                #pragma unroll
                for (int e = 0; e < 4; e++) s[i][e] = 0.f;

            #pragma unroll
            for (int kf = 0; kf < 8; kf++) {
                const int kb = kf * 8;
                uint32_t a[4];
                const float* pa = Qs + (mbase + gid) * ALD + kb + tg;
                a[0] = f2tf32(pa[0]);
                a[1] = f2tf32(pa[8 * ALD]);
                a[2] = f2tf32(pa[4]);
                a[3] = f2tf32(pa[8 * ALD + 4]);
                #pragma unroll
                for (int nt = 0; nt < 8; nt++) {
                    uint32_t bf[2];
                    const float* pb = Ks + (nt * 8 + gid) * ALD + kb + tg;
                    bf[0] = f2tf32(pb[0]);
                    bf[1] = f2tf32(pb[4]);
                    mma_tf32(s[nt], a, bf);
                }
            }

            // ---- online softmax on fragment rows gid / gid+8 ----
            float mx0 = -1e30f, mx1 = -1e30f;
            #pragma unroll
            for (int nt = 0; nt < 8; nt++) {
                mx0 = fmaxf(mx0, fmaxf(s[nt][0], s[nt][1]));
                mx1 = fmaxf(mx1, fmaxf(s[nt][2], s[nt][3]));
            }
            mx0 = fmaxf(mx0, __shfl_xor_sync(0xffffffffu, mx0, 1));
            mx0 = fmaxf(mx0, __shfl_xor_sync(0xffffffffu, mx0, 2));
            mx1 = fmaxf(mx1, __shfl_xor_sync(0xffffffffu, mx1, 1));
            mx1 = fmaxf(mx1, __shfl_xor_sync(0xffffffffu, mx1, 2));

            const float mn0 = fmaxf(m0, mx0), mn1 = fmaxf(m1, mx1);
            const float cr0 = __expf(m0 - mn0), cr1 = __expf(m1 - mn1);
            float sum0 = 0.f, sum1 = 0.f;
            float* pr0 = Ps + (mbase + gid) * ALD + 2 * tg;
            float* pr1 = pr0 + 8 * ALD;
            #pragma unroll
            for (int nt = 0; nt < 8; nt++) {
                float p00 = __expf(s[nt][0] - mn0);
                float p01 = __expf(s[nt][1] - mn0);
                float p10 = __expf(s[nt][2] - mn1);
                float p11 = __expf(s[nt][3] - mn1);
                sum0 += p00 + p01;
                sum1 += p10 + p11;
                *(float2*)(pr0 + nt * 8) = make_float2(p00, p01);
                *(float2*)(pr1 + nt * 8) = make_float2(p10, p11);
            }
            sum0 += __shfl_xor_sync(0xffffffffu, sum0, 1);
            sum0 += __shfl_xor_sync(0xffffffffu, sum0, 2);
            sum1 += __shfl_xor_sync(0xffffffffu, sum1, 1);
            sum1 += __shfl_xor_sync(0xffffffffu, sum1, 2);

            m0 = mn0; m1 = mn1;
            l0 = l0 * cr0 + sum0;
            l1 = l1 * cr1 + sum1;
            #pragma unroll
            for (int nt = 0; nt < 8; nt++) {
                o[nt][0] *= cr0; o[nt][1] *= cr0;
                o[nt][2] *= cr1; o[nt][3] *= cr1;
            }
            __syncwarp();   // Ps rows are warp-private

            // ---- O += P * V ----
            #pragma unroll
            for (int kf = 0; kf < 8; kf++) {
                const int kb = kf * 8;
                uint32_t a[4];
                const float* pa = Ps + (mbase + gid) * ALD + kb + tg;
                a[0] = f2tf32(pa[0]);
                a[1] = f2tf32(pa[8 * ALD]);
                a[2] = f2tf32(pa[4]);
                a[3] = f2tf32(pa[8 * ALD + 4]);
                #pragma unroll
                for (int nt = 0; nt < 8; nt++) {
                    uint32_t bf[2];
                    const float* pb = Vs + (kb + tg) * ALD + nt * 8 + gid;
                    bf[0] = f2tf32(pb[0]);
                    bf[1] = f2tf32(pb[4 * ALD]);
                    mma_tf32(o[nt], a, bf);
                }
            }
        }
    }

    // ---- epilogue ----
    const float inv0 = 1.f / l0, inv1 = 1.f / l1;
    float* ob = O + ((size_t)(b * SEQ + qt * QROWS + mbase)) * HID + h * HD;
    #pragma unroll
    for (int nt = 0; nt < 8; nt++) {
        const int col = nt * 8 + 2 * tg;
        *(float2*)(ob + (size_t)gid * HID + col) =
            make_float2(o[nt][0] * inv0, o[nt][1] * inv0);
        *(float2*)(ob + (size_t)(gid + 8) * HID + col) =
            make_float2(o[nt][2] * inv1, o[nt][3] * inv1);
    }
}

// ---------------------------------------------------------------------------
extern "C" void kernel_launch(void* const* d_in, const int* in_sizes, int n_in,
                              void* d_out, int out_size) {
    const float* X  = (const float*)d_in[0];
    const float* Wq = (const float*)d_in[1];
    const float* bq = (const float*)d_in[2];
    const float* Wk = (const float*)d_in[3];
    const float* bk = (const float*)d_in[4];
    const float* Wv = (const float*)d_in[5];
    const float* bv = (const float*)d_in[6];
    const float* Wo = (const float*)d_in[7];
    const float* bo = (const float*)d_in[8];
    float* out = (float*)d_out;

    float *Qp, *Kp, *Vp, *Ap;
    cudaGetSymbolAddress((void**)&Qp, g_Q);
    cudaGetSymbolAddress((void**)&Kp, g_K);
    cudaGetSymbolAddress((void**)&Vp, g_V);
    cudaGetSymbolAddress((void**)&Ap, g_A);

    cudaFuncSetAttribute(gemm_tf32_kernel,
                         cudaFuncAttributeMaxDynamicSharedMemorySize, GM_SMEM);
    cudaFuncSetAttribute(attn_kernel,
                         cudaFuncAttributeMaxDynamicSharedMemorySize, AT_SMEM);

    dim3 gg(HID / BN, NTOK / BM);  // (8, 32) = 256 CTAs
    gemm_tf32_kernel<<<gg, 256, GM_SMEM>>>(X, Wq, bq, Qp);
    gemm_tf32_kernel<<<gg, 256, GM_SMEM>>>(X, Wk, bk, Kp);
    gemm_tf32_kernel<<<gg, 256, GM_SMEM>>>(X, Wv, bv, Vp);

    attn_kernel<<<dim3(SEQ / QROWS, HEADS, BS_), 256, AT_SMEM>>>(Qp, Kp, Vp, Ap);

    gemm_tf32_kernel<<<gg, 256, GM_SMEM>>>(Ap, Wo, bo, out);
}